// round 1
// baseline (speedup 1.0000x reference)
#include <cuda_runtime.h>

#define BB   2
#define HH   8
#define PP   128
#define HIDD 1024
#define KWIN 512

// Scratch (no allocations allowed in kernel_launch)
__device__ float g_dteff[BB][KWIN][HH];   // dt_eff for the last KWIN steps
__device__ float g_y[BB][HH][PP];         // SSD output at t = T-1
__device__ float g_z[BB][HIDD];           // normalized gated output

// ---------------------------------------------------------------------------
// Kernel 1: dt_eff[b, s, h] = hidden[b,s,:] . dt_W[h,:] + dt_b[h] + dt_bias[h]
// for s in [T-KWIN, T). One warp per (b,s); dt_W cached in smem.
// ---------------------------------------------------------------------------
__global__ void k_dt(const float* __restrict__ hidden,
                     const float* __restrict__ dt_W,
                     const float* __restrict__ dt_b,
                     const float* __restrict__ dt_bias,
                     int T, int s0) {
    __shared__ float w_sh[HH * HIDD];   // 32 KB
    int tid = threadIdx.x;
    for (int i = tid; i < HH * HIDD; i += blockDim.x) w_sh[i] = dt_W[i];
    __syncthreads();

    int warp = tid >> 5, lane = tid & 31;
    int nw = blockDim.x >> 5;                 // 8 warps
    int widx = blockIdx.x * nw + warp;        // 0 .. BB*KWIN-1
    int b  = widx / KWIN;
    int si = widx % KWIN;
    int s  = s0 + si;

    const float* xrow = hidden + ((size_t)b * T + s) * HIDD;
    float acc[HH];
    #pragma unroll
    for (int h = 0; h < HH; h++) acc[h] = 0.f;
    for (int e = lane; e < HIDD; e += 32) {
        float x = xrow[e];
        #pragma unroll
        for (int h = 0; h < HH; h++) acc[h] += x * w_sh[h * HIDD + e];
    }
    #pragma unroll
    for (int h = 0; h < HH; h++) {
        float v = acc[h];
        #pragma unroll
        for (int o = 16; o > 0; o >>= 1) v += __shfl_xor_sync(0xffffffffu, v, o);
        if (lane == 0) g_dteff[b][si][h] = v + dt_b[h] + dt_bias[h];
    }
}

// ---------------------------------------------------------------------------
// Kernel 2: per (b,h) block. Computes
//   dots[s]  = x[b,T-1,h,:] . x[b,s,h,:]
//   c[s]     = sum_{r=s+1..T-1} dA[r]            (suffix scan of dA)
//   w[s]     = dots[s] * exp(c[s]) * dt_eff[s]
//   y[p]     = sum_s w[s] * x[b,s,h,p] + D[h] * x[b,T-1,h,p]
// ---------------------------------------------------------------------------
__global__ void k_scan(const float* __restrict__ hidden,
                       const float* __restrict__ A_log,
                       const float* __restrict__ Dv,
                       int T, int s0) {
    int b = blockIdx.x / HH;
    int h = blockIdx.x % HH;

    __shared__ float dots[KWIN];
    __shared__ float wv[KWIN];
    __shared__ float sc[KWIN];
    __shared__ float xlast[PP];
    __shared__ float ypart[2][PP];

    int tid = threadIdx.x;                    // 256 threads
    int warp = tid >> 5, lane = tid & 31;
    float Ah = -__expf(A_log[h]);

    if (tid < PP)
        xlast[tid] = hidden[((size_t)b * T + (T - 1)) * HIDD + h * PP + tid];
    __syncthreads();

    // Phase A: dots (one warp per s, strided)
    for (int s = warp; s < KWIN; s += 8) {
        const float* xs = hidden + ((size_t)b * T + s0 + s) * HIDD + h * PP;
        float v = 0.f;
        #pragma unroll
        for (int e = lane; e < PP; e += 32) v += xs[e] * xlast[e];
        #pragma unroll
        for (int o = 16; o > 0; o >>= 1) v += __shfl_xor_sync(0xffffffffu, v, o);
        if (lane == 0) dots[s] = v;
    }
    // Load reversed dA for the suffix scan: sc[j] = dA[KWIN-1-j]
    for (int j = tid; j < KWIN; j += 256)
        sc[j] = g_dteff[b][KWIN - 1 - j][h] * Ah;
    __syncthreads();

    // Phase B: inclusive Hillis-Steele prefix scan of sc (length 512, 2 elems/thread)
    for (int off = 1; off < KWIN; off <<= 1) {
        int j0 = tid, j1 = tid + 256;
        float t0 = (j0 >= off) ? sc[j0 - off] : 0.f;
        float t1 = sc[j1 - off];               // j1 >= 256 >= off always
        __syncthreads();
        if (j0 >= off) sc[j0] += t0;
        sc[j1] += t1;
        __syncthreads();
    }
    // sc[j] = sum_{s=KWIN-1-j .. KWIN-1} dA[s];  c[s] = sc[KWIN-2-s], c[KWIN-1] = 0
    for (int s = tid; s < KWIN; s += 256) {
        float c = (s == KWIN - 1) ? 0.f : sc[KWIN - 2 - s];
        wv[s] = dots[s] * __expf(c) * g_dteff[b][s][h];
    }
    __syncthreads();

    // Phase C: y[p] = sum_s wv[s] * x[s,p]   (two s-halves, 128 p-lanes each)
    int p = tid & 127, half = tid >> 7;
    float acc = 0.f;
    const float* base = hidden + ((size_t)b * T + s0) * HIDD + h * PP + p;
    for (int s = half * 256; s < half * 256 + 256; s++)
        acc += wv[s] * base[(size_t)s * HIDD];
    ypart[half][p] = acc;
    __syncthreads();
    if (tid < PP)
        g_y[b][h][tid] = ypart[0][tid] + ypart[1][tid] + Dv[h] * xlast[tid];
}

// ---------------------------------------------------------------------------
// Kernel 3: per-batch block. gate -> silu -> z -> RMSNorm -> g_z
// ---------------------------------------------------------------------------
__global__ void k_norm(const float* __restrict__ hidden,
                       const float* __restrict__ g_W,
                       const float* __restrict__ g_b,
                       const float* __restrict__ norm_w,
                       int T) {
    int b = blockIdx.x;
    __shared__ float silu_g[HH];
    __shared__ float red[8];
    __shared__ float scale_sh;

    int tid = threadIdx.x, warp = tid >> 5, lane = tid & 31;
    const float* xl = hidden + ((size_t)b * T + (T - 1)) * HIDD;

    // One warp per head: gate dot
    {
        const float* w = g_W + warp * HIDD;
        float v = 0.f;
        for (int e = lane; e < HIDD; e += 32) v += xl[e] * w[e];
        #pragma unroll
        for (int o = 16; o > 0; o >>= 1) v += __shfl_xor_sync(0xffffffffu, v, o);
        if (lane == 0) {
            float g = tanhf(v + g_b[warp]);
            silu_g[warp] = g / (1.f + __expf(-g));
        }
    }
    __syncthreads();

    float zloc[4];
    float ssq = 0.f;
    #pragma unroll
    for (int k = 0; k < 4; k++) {
        int i = tid + k * 256;
        int h = i >> 7;
        float z = g_y[b][h][i & 127] * silu_g[h];
        zloc[k] = z;
        ssq += z * z;
    }
    #pragma unroll
    for (int o = 16; o > 0; o >>= 1) ssq += __shfl_xor_sync(0xffffffffu, ssq, o);
    if (lane == 0) red[warp] = ssq;
    __syncthreads();
    if (tid == 0) {
        float s = 0.f;
        #pragma unroll
        for (int i = 0; i < 8; i++) s += red[i];
        scale_sh = rsqrtf(s / (float)HIDD + 1e-5f);
    }
    __syncthreads();
    float sc = scale_sh;
    #pragma unroll
    for (int k = 0; k < 4; k++) {
        int i = tid + k * 256;
        g_z[b][i] = zloc[k] * sc * norm_w[i];
    }
}

// ---------------------------------------------------------------------------
// Kernel 4: per (b,h) block. o[b,h,q] = sum_p z[b,h,p] * o_W[h,p,q] + o_b[h,q]
// ---------------------------------------------------------------------------
__global__ void k_proj(const float* __restrict__ o_W,
                       const float* __restrict__ o_b,
                       float* __restrict__ out) {
    int b = blockIdx.x / HH, h = blockIdx.x % HH;
    __shared__ float zsh[PP];
    __shared__ float opart[2][PP];
    int tid = threadIdx.x;
    if (tid < PP) zsh[tid] = g_z[b][h * PP + tid];
    __syncthreads();
    int q = tid & 127, half = tid >> 7;
    const float* W = o_W + (size_t)h * PP * PP;
    float acc = 0.f;
    for (int p = half * 64; p < half * 64 + 64; p++)
        acc += zsh[p] * W[p * PP + q];
    opart[half][q] = acc;
    __syncthreads();
    if (tid < PP)
        out[b * HIDD + h * PP + tid] = opart[0][tid] + opart[1][tid] + o_b[h * PP + tid];
}

extern "C" void kernel_launch(void* const* d_in, const int* in_sizes, int n_in,
                              void* d_out, int out_size) {
    const float* hidden  = (const float*)d_in[0];
    const float* dt_W    = (const float*)d_in[1];
    const float* dt_b    = (const float*)d_in[2];
    const float* g_W     = (const float*)d_in[3];
    const float* g_bv    = (const float*)d_in[4];
    const float* A_log   = (const float*)d_in[5];
    const float* Dv      = (const float*)d_in[6];
    const float* dt_bias = (const float*)d_in[7];
    const float* norm_w  = (const float*)d_in[8];
    const float* o_W     = (const float*)d_in[9];
    const float* o_bv    = (const float*)d_in[10];

    int T  = in_sizes[0] / (BB * HIDD);   // 4096
    int s0 = T - KWIN;

    k_dt  <<<BB * KWIN / 8, 256>>>(hidden, dt_W, dt_b, dt_bias, T, s0);
    k_scan<<<BB * HH,       256>>>(hidden, A_log, Dv, T, s0);
    k_norm<<<BB,            256>>>(hidden, g_W, g_bv, norm_w, T);
    k_proj<<<BB * HH,       256>>>(o_W, o_bv, (float*)d_out);
}

// round 4
// speedup vs baseline: 2.1270x; 2.1270x over previous
#include <cuda_runtime.h>

#define BB   2
#define HH   8
#define PP   128
#define HIDD 1024
#define KWIN 128

__device__ float g_y[BB][HH][PP];   // SSD output at t = T-1

// ---------------------------------------------------------------------------
// Kernel 1: per (b,h) block (256 thr). Window SSD collapse for the last step.
//   dte[s]  = x[b,s,:]·dt_W[h] + dt_b[h] + dt_bias[h]
//   dots[s] = x[b,s,h,:]·x[b,T-1,h,:]
//   c[s]    = suffix-sum of dA; wv[s] = dots*exp(c)*dte
//   g_y[p]  = Σ_s wv[s]·x[b,s,h,p] + D[h]·xlast[p]
// ---------------------------------------------------------------------------
__global__ void __launch_bounds__(256, 1)
k_window(const float* __restrict__ hidden,
         const float* __restrict__ dt_W,
         const float* __restrict__ dt_b,
         const float* __restrict__ A_log,
         const float* __restrict__ Dv,
         const float* __restrict__ dt_bias,
         int T) {
    int b = blockIdx.x >> 3, h = blockIdx.x & 7;
    int tid = threadIdx.x, warp = tid >> 5, lane = tid & 31;
    int s0 = T - KWIN;

    __shared__ float4 wsh4[HIDD / 4];      // dt_W[h] as float4
    __shared__ float4 xlast4[PP / 4];      // head slice of last row
    __shared__ float  dte[KWIN], dots[KWIN], sc[KWIN], wv[KWIN];
    __shared__ float  part[2][PP];

    {
        const float4* w4 = (const float4*)(dt_W + (size_t)h * HIDD);
        for (int i = tid; i < HIDD / 4; i += 256) wsh4[i] = w4[i];
        const float4* xl4 = (const float4*)(hidden + ((size_t)b * T + T - 1) * HIDD + h * PP);
        if (tid < PP / 4) xlast4[tid] = xl4[tid];
    }
    __syncthreads();

    float Ah   = -__expf(A_log[h]);
    float bias = dt_b[h] + dt_bias[h];

    // Phase A: dte + dots, one warp per s (float4 vectorized)
    for (int s = warp; s < KWIN; s += 8) {
        const float4* xr4 = (const float4*)(hidden + ((size_t)b * T + s0 + s) * HIDD);
        float v = 0.f;
        #pragma unroll
        for (int k = 0; k < 8; k++) {
            float4 a = xr4[lane + 32 * k], w = wsh4[lane + 32 * k];
            v += a.x * w.x + a.y * w.y + a.z * w.z + a.w * w.w;
        }
        float4 ahd = xr4[h * (PP / 4) + lane], xw = xlast4[lane];
        float d = ahd.x * xw.x + ahd.y * xw.y + ahd.z * xw.z + ahd.w * xw.w;
        #pragma unroll
        for (int o = 16; o > 0; o >>= 1) {
            v += __shfl_xor_sync(0xffffffffu, v, o);
            d += __shfl_xor_sync(0xffffffffu, d, o);
        }
        if (lane == 0) { dte[s] = v + bias; dots[s] = d; }
    }
    __syncthreads();

    // Phase B: reversed inclusive prefix scan of dA (length 128)
    if (tid < KWIN) sc[tid] = dte[KWIN - 1 - tid] * Ah;
    __syncthreads();
    for (int off = 1; off < KWIN; off <<= 1) {
        float t = 0.f;
        if (tid < KWIN && tid >= off) t = sc[tid - off];
        __syncthreads();
        if (tid < KWIN && tid >= off) sc[tid] += t;
        __syncthreads();
    }
    if (tid < KWIN) {
        float c = (tid == KWIN - 1) ? 0.f : sc[KWIN - 2 - tid];
        wv[tid] = dots[tid] * __expf(c) * dte[tid];
    }
    __syncthreads();

    // Phase C: weighted column reduction (rows are L2-hot from Phase A)
    int q = tid & 127, hf = tid >> 7;
    {
        const float* base = hidden + ((size_t)b * T + s0 + hf * 64) * HIDD + h * PP + q;
        float acc = 0.f;
        for (int s = 0; s < 64; s++) acc += wv[hf * 64 + s] * base[(size_t)s * HIDD];
        part[hf][q] = acc;
    }
    __syncthreads();
    if (tid < PP) {
        const float* xl = hidden + ((size_t)b * T + T - 1) * HIDD + h * PP;
        g_y[b][h][tid] = part[0][tid] + part[1][tid] + Dv[h] * xl[tid];
    }
}

// ---------------------------------------------------------------------------
// Kernel 2: per (b,h) block (256 thr). Redundant gate+RMSNorm per block
// (cheap, removes any cross-block sync), then own-head 128x128 projection
// with o_W register-prefetched to overlap the norm math.
// ---------------------------------------------------------------------------
__global__ void __launch_bounds__(256, 1)
k_out(const float* __restrict__ hidden,
      const float* __restrict__ g_W,
      const float* __restrict__ g_bv,
      const float* __restrict__ norm_w,
      const float* __restrict__ o_W,
      const float* __restrict__ o_bv,
      float* __restrict__ out, int T) {
    int b = blockIdx.x >> 3, h = blockIdx.x & 7;
    int tid = threadIdx.x, warp = tid >> 5, lane = tid & 31;
    int q = tid & 127, hf = tid >> 7;

    __shared__ float silu_sh[HH];
    __shared__ float red[8];
    __shared__ float scsh;
    __shared__ float zsh[PP];
    __shared__ float part[2][PP];

    // Prefetch o_W tile early; LDGs retire while we do the norm math.
    float Wreg[64];
    {
        const float* Wp = o_W + ((size_t)h * PP + hf * 64) * PP + q;
        #pragma unroll
        for (int i = 0; i < 64; i++) Wreg[i] = Wp[(size_t)i * PP];
    }

    // Gate: one warp per head, float4 dot over the last hidden row
    {
        const float4* xl4 = (const float4*)(hidden + ((size_t)b * T + T - 1) * HIDD);
        const float4* w4  = (const float4*)(g_W + (size_t)warp * HIDD);
        float v = 0.f;
        #pragma unroll
        for (int k = 0; k < 8; k++) {
            float4 a = xl4[lane + 32 * k], w = w4[lane + 32 * k];
            v += a.x * w.x + a.y * w.y + a.z * w.z + a.w * w.w;
        }
        #pragma unroll
        for (int o = 16; o > 0; o >>= 1) v += __shfl_xor_sync(0xffffffffu, v, o);
        if (lane == 0) {
            float g = tanhf(v + g_bv[warp]);
            silu_sh[warp] = g / (1.f + __expf(-g));
        }
    }
    __syncthreads();

    // RMS sum over all 1024 gated values (each block redundantly)
    float ssq = 0.f;
    #pragma unroll
    for (int k = 0; k < 4; k++) {
        int i = tid + k * 256;
        int hh = i >> 7;
        float z = g_y[b][hh][i & 127] * silu_sh[hh];
        ssq += z * z;
    }
    #pragma unroll
    for (int o = 16; o > 0; o >>= 1) ssq += __shfl_xor_sync(0xffffffffu, ssq, o);
    if (lane == 0) red[warp] = ssq;
    __syncthreads();
    if (tid == 0) {
        float s = 0.f;
        #pragma unroll
        for (int i = 0; i < 8; i++) s += red[i];
        scsh = rsqrtf(s / (float)HIDD + 1e-5f);
    }
    __syncthreads();

    // Own-head normalized z
    if (tid < PP)
        zsh[tid] = g_y[b][h][tid] * silu_sh[h] * scsh * norm_w[h * PP + tid];
    __syncthreads();

    // Projection: out[q] = sum_p z[p] * o_W[h,p,q] + o_b[h,q]
    float acc = 0.f;
    #pragma unroll
    for (int i = 0; i < 64; i++) acc += Wreg[i] * zsh[hf * 64 + i];
    part[hf][q] = acc;
    __syncthreads();
    if (tid < PP)
        out[b * HIDD + h * PP + tid] = part[0][tid] + part[1][tid] + o_bv[h * PP + tid];
}

extern "C" void kernel_launch(void* const* d_in, const int* in_sizes, int n_in,
                              void* d_out, int out_size) {
    const float* hidden  = (const float*)d_in[0];
    const float* dt_W    = (const float*)d_in[1];
    const float* dt_b    = (const float*)d_in[2];
    const float* g_W     = (const float*)d_in[3];
    const float* g_bv    = (const float*)d_in[4];
    const float* A_log   = (const float*)d_in[5];
    const float* Dv      = (const float*)d_in[6];
    const float* dt_bias = (const float*)d_in[7];
    const float* norm_w  = (const float*)d_in[8];
    const float* o_W     = (const float*)d_in[9];
    const float* o_bv    = (const float*)d_in[10];

    int T = in_sizes[0] / (BB * HIDD);   // 4096

    k_window<<<BB * HH, 256>>>(hidden, dt_W, dt_b, A_log, Dv, dt_bias, T);
    k_out   <<<BB * HH, 256>>>(hidden, g_W, g_bv, norm_w, o_W, o_bv, (float*)d_out, T);
}